// round 8
// baseline (speedup 1.0000x reference)
#include <cuda_runtime.h>
#include <cuda_bf16.h>
#include <cstdint>

// REWAEncoder: out = (FWHT_128(x @ W^T)/sqrt(128) > 0)
// R8: mma.sync m16n8k16 BF16 3-way split (x1W1+x1W2+x2W1, fp32 accum)
//     + FWHT + sign. Rows with min|h| < TAU recomputed bit-exactly with the
//     reference sequential fp32 fma chain (machinery verified rel_err 0.0 in R7).
//
// x [32768,1024] f32, W [128,1024] f32, out [32768,128] f32.

#define K_DIM 1024
#define MOUT  128
#define NROWS 32768
#define TAU   4e-4f

#define TPITCH 80                 // smem row pitch bytes (40 bf16), conflict-free
#define TILEB  (128 * TPITCH)    // 10240 B per component tile
#define BUFB   (4 * TILEB)       // X1,X2,W1,W2
#define SM_TOTAL 81920           // 2 buffers (FWHT overlay needs 67584 <= this)

__device__ __align__(16) uint16_t g_W1[MOUT * K_DIM];
__device__ __align__(16) uint16_t g_W2[MOUT * K_DIM];
__device__ int g_flags[NROWS];

__device__ __forceinline__ uint32_t smem_u32(const void* p) {
    uint32_t a;
    asm("{ .reg .u64 t; cvta.to.shared.u64 t, %1; cvt.u32.u64 %0, t; }"
        : "=r"(a) : "l"(p));
    return a;
}
__device__ __forceinline__ void cpa16(uint32_t dst, const void* src) {
    asm volatile("cp.async.ca.shared.global [%0], [%1], 16;"
                 :: "r"(dst), "l"(src) : "memory");
}
__device__ __forceinline__ void ldsm_x4(uint32_t* r, uint32_t addr) {
    asm volatile("ldmatrix.sync.aligned.m8n8.x4.shared.b16 {%0,%1,%2,%3}, [%4];"
                 : "=r"(r[0]), "=r"(r[1]), "=r"(r[2]), "=r"(r[3]) : "r"(addr));
}
__device__ __forceinline__ void mma_bf16(float* c, const uint32_t* a,
                                         const uint32_t* b) {
    asm volatile(
        "mma.sync.aligned.m16n8k16.row.col.f32.bf16.bf16.f32 "
        "{%0,%1,%2,%3}, {%4,%5,%6,%7}, {%8,%9}, {%0,%1,%2,%3};"
        : "+f"(c[0]), "+f"(c[1]), "+f"(c[2]), "+f"(c[3])
        : "r"(a[0]), "r"(a[1]), "r"(a[2]), "r"(a[3]), "r"(b[0]), "r"(b[1]));
}
__device__ __forceinline__ void split2(float f0, float f1,
                                       uint32_t& p1, uint32_t& p2) {
    __nv_bfloat16 h0 = __float2bfloat16(f0);
    __nv_bfloat16 h1 = __float2bfloat16(f1);
    __nv_bfloat16 l0 = __float2bfloat16(f0 - __bfloat162float(h0));
    __nv_bfloat16 l1 = __float2bfloat16(f1 - __bfloat162float(h1));
    p1 = (uint32_t)__bfloat16_as_ushort(h0) | ((uint32_t)__bfloat16_as_ushort(h1) << 16);
    p2 = (uint32_t)__bfloat16_as_ushort(l0) | ((uint32_t)__bfloat16_as_ushort(l1) << 16);
}

// ---------------- prep: split W into bf16 head/residual ----------------
__global__ void split_w_kernel(const float* __restrict__ W) {
    const int i = blockIdx.x * blockDim.x + threadIdx.x;
    const float w = W[i];
    const __nv_bfloat16 h = __float2bfloat16(w);
    const __nv_bfloat16 l = __float2bfloat16(w - __bfloat162float(h));
    g_W1[i] = __bfloat16_as_ushort(h);
    g_W2[i] = __bfloat16_as_ushort(l);
}

// ---------------- main: bf16-split mma GEMM + FWHT + sign + flag ----------
__global__ void __launch_bounds__(256, 2)
tensor_gemm_kernel(const float* __restrict__ x, float* __restrict__ out) {
    extern __shared__ __align__(16) char smem[];
    const uint32_t sb = smem_u32(smem);

    const int tid  = threadIdx.x;
    const int wid  = tid >> 5;
    const int lane = tid & 31;
    const int tg   = lane & 3;
    const int g    = lane >> 2;
    const int warpM = wid & 3;        // m-base warpM*32
    const int warpN = wid >> 2;       // n-base warpN*64
    const int block_row = blockIdx.x * 128;

    // staging: thread -> (row 0..127, 16-elem half)
    const int srow  = tid >> 1;
    const int shalf = tid & 1;
    const float*    xrow = x + (size_t)(block_row + srow) * K_DIM + shalf * 16;
    const uint16_t* w1p  = g_W1 + (size_t)srow * K_DIM + shalf * 16;
    const uint16_t* w2p  = g_W2 + (size_t)srow * K_DIM + shalf * 16;
    const uint32_t  sdst = srow * TPITCH + shalf * 32;   // byte offset in tile

    // ldmatrix lane addressing (byte offsets within a tile)
    const int aOff = (warpM * 32 + (lane & 15)) * TPITCH + (lane >> 4) * 16;
    const int bOff = (warpN * 64 + (lane & 7) + ((lane & 16) ? 8 : 0)) * TPITCH
                   + ((lane >> 3) & 1) * 16;

    float acc[2][8][4];
#pragma unroll
    for (int mi = 0; mi < 2; ++mi)
#pragma unroll
        for (int ni = 0; ni < 8; ++ni)
#pragma unroll
            for (int r = 0; r < 4; ++r) acc[mi][ni][r] = 0.0f;

    // prologue: W(0) -> buf0 via cp.async; x(0) raw -> regs -> packed
    {
        const uint32_t wb1 = sb + 2 * TILEB, wb2 = sb + 3 * TILEB;
        cpa16(wb1 + sdst,      w1p);     cpa16(wb1 + sdst + 16, w1p + 8);
        cpa16(wb2 + sdst,      w2p);     cpa16(wb2 + sdst + 16, w2p + 8);
        asm volatile("cp.async.commit_group;" ::: "memory");
    }
    float4 rx[4];
    uint32_t px1[8], px2[8];
#pragma unroll
    for (int i = 0; i < 4; ++i) rx[i] = *(const float4*)(xrow + i * 4);
#pragma unroll
    for (int i = 0; i < 4; ++i) {
        split2(rx[i].x, rx[i].y, px1[2 * i], px2[2 * i]);
        split2(rx[i].z, rx[i].w, px1[2 * i + 1], px2[2 * i + 1]);
    }

    for (int c = 0; c < 32; ++c) {
        const uint32_t cb = sb + (uint32_t)(c & 1) * BUFB;
        __syncthreads();    // all reads of this buffer (iter c-2) and W target (c-1) done

        // STS packed x(c)
        *(uint4*)(smem + (cb - sb) + sdst)          = *(uint4*)&px1[0];
        *(uint4*)(smem + (cb - sb) + sdst + 16)     = *(uint4*)&px1[4];
        *(uint4*)(smem + (cb - sb) + TILEB + sdst)      = *(uint4*)&px2[0];
        *(uint4*)(smem + (cb - sb) + TILEB + sdst + 16) = *(uint4*)&px2[4];

        const bool more = (c + 1 < 32);
        if (more) {
            const uint32_t nb = sb + (uint32_t)((c + 1) & 1) * BUFB;
            const uint32_t wb1 = nb + 2 * TILEB, wb2 = nb + 3 * TILEB;
            cpa16(wb1 + sdst,      w1p + (c + 1) * 32);
            cpa16(wb1 + sdst + 16, w1p + (c + 1) * 32 + 8);
            cpa16(wb2 + sdst,      w2p + (c + 1) * 32);
            cpa16(wb2 + sdst + 16, w2p + (c + 1) * 32 + 8);
            asm volatile("cp.async.commit_group;" ::: "memory");
#pragma unroll
            for (int i = 0; i < 4; ++i)
                rx[i] = *(const float4*)(xrow + (c + 1) * 32 + i * 4);
            asm volatile("cp.async.wait_group 1;" ::: "memory");   // W(c) arrived
        } else {
            asm volatile("cp.async.wait_group 0;" ::: "memory");
        }
        __syncthreads();

        // compute chunk c: 2 k-steps of 16
        const uint32_t xb1 = cb, xb2 = cb + TILEB;
        const uint32_t wb1 = cb + 2 * TILEB, wb2 = cb + 3 * TILEB;
#pragma unroll
        for (int s = 0; s < 2; ++s) {
            const int s32 = s * 32;     // 16 bf16 = 32 bytes
            uint32_t A1[2][4], A2[2][4], B[4][4];
            ldsm_x4(A1[0], xb1 + aOff + s32);
            ldsm_x4(A1[1], xb1 + aOff + 16 * TPITCH + s32);
            ldsm_x4(A2[0], xb2 + aOff + s32);
            ldsm_x4(A2[1], xb2 + aOff + 16 * TPITCH + s32);
#pragma unroll
            for (int q = 0; q < 4; ++q)
                ldsm_x4(B[q], wb1 + bOff + q * 16 * TPITCH + s32);
#pragma unroll
            for (int mi = 0; mi < 2; ++mi)
#pragma unroll
                for (int q = 0; q < 4; ++q) {
                    mma_bf16(acc[mi][2 * q],     A1[mi], &B[q][0]);
                    mma_bf16(acc[mi][2 * q + 1], A1[mi], &B[q][2]);
                    mma_bf16(acc[mi][2 * q],     A2[mi], &B[q][0]);
                    mma_bf16(acc[mi][2 * q + 1], A2[mi], &B[q][2]);
                }
#pragma unroll
            for (int q = 0; q < 4; ++q)
                ldsm_x4(B[q], wb2 + bOff + q * 16 * TPITCH + s32);
#pragma unroll
            for (int mi = 0; mi < 2; ++mi)
#pragma unroll
                for (int q = 0; q < 4; ++q) {
                    mma_bf16(acc[mi][2 * q],     A1[mi], &B[q][0]);
                    mma_bf16(acc[mi][2 * q + 1], A1[mi], &B[q][2]);
                }
        }

        if (more) {
#pragma unroll
            for (int i = 0; i < 4; ++i) {
                split2(rx[i].x, rx[i].y, px1[2 * i], px2[2 * i]);
                split2(rx[i].z, rx[i].w, px1[2 * i + 1], px2[2 * i + 1]);
            }
        }
    }
    __syncthreads();

    // ---- epilogue: FWHT (reference order, fp32) + sign + flag ----
    float (*hb)[132] = reinterpret_cast<float(*)[132]>(smem);
    const float scale = 0.08838834764831844f;   // fp32(1/sqrt(128))

    for (int hs = 0; hs < 2; ++hs) {
        if ((warpM >> 1) == hs) {
            const int lr0 = (warpM & 1) * 32;
#pragma unroll
            for (int mi = 0; mi < 2; ++mi)
#pragma unroll
                for (int ni = 0; ni < 8; ++ni)
#pragma unroll
                    for (int r = 0; r < 4; ++r) {
                        const int lr = lr0 + mi * 16 + g + 8 * (r >> 1);
                        const int cc = warpN * 64 + ni * 8 + tg * 2 + (r & 1);
                        hb[lr][cc] = acc[mi][ni][r];
                    }
        }
        __syncthreads();

        for (int half = 1; half < MOUT; half <<= 1) {
#pragma unroll
            for (int p = 0; p < 16; ++p) {
                const int pidx = tid + p * 256;
                const int row = pidx >> 6;
                const int t   = pidx & 63;
                const int j   = ((t & ~(half - 1)) << 1) | (t & (half - 1));
                const float a = hb[row][j];
                const float b = hb[row][j + half];
                hb[row][j]        = a + b;
                hb[row][j + half] = a - b;
            }
            __syncthreads();
        }

        const int r  = tid >> 2;
        const int cb2 = (tid & 3) * 32;
        float mn = 1e30f;
#pragma unroll
        for (int cc = 0; cc < 32; cc += 4) {
            const float4 v = *(const float4*)&hb[r][cb2 + cc];
            const float s0 = v.x * scale, s1 = v.y * scale,
                        s2 = v.z * scale, s3 = v.w * scale;
            float4 o;
            o.x = s0 > 0.0f ? 1.0f : 0.0f;
            o.y = s1 > 0.0f ? 1.0f : 0.0f;
            o.z = s2 > 0.0f ? 1.0f : 0.0f;
            o.w = s3 > 0.0f ? 1.0f : 0.0f;
            mn = fminf(mn, fminf(fminf(fabsf(s0), fabsf(s1)),
                                 fminf(fabsf(s2), fabsf(s3))));
            *(float4*)(out + (size_t)(block_row + hs * 64 + r) * MOUT + cb2 + cc) = o;
        }
        mn = fminf(mn, __shfl_xor_sync(0xffffffffu, mn, 1));
        mn = fminf(mn, __shfl_xor_sync(0xffffffffu, mn, 2));
        if ((tid & 3) == 0) g_flags[block_row + hs * 64 + r] = (mn < TAU) ? 1 : 0;
        __syncthreads();
    }
}

// ---------------- exact fix: one block per row, bit-exact reference chain ----
__global__ void __launch_bounds__(128)
fix_rows_kernel(const float* __restrict__ x, const float* __restrict__ W,
                float* __restrict__ out) {
    const int row = blockIdx.x;
    if (!g_flags[row]) return;

    __shared__ float xs[K_DIM];
    __shared__ float hrow[MOUT];
    const int t = threadIdx.x;

    for (int cc = t; cc < K_DIM / 4; cc += 128)
        *(float4*)&xs[cc * 4] = *(const float4*)&x[(size_t)row * K_DIM + cc * 4];
    __syncthreads();

    float acc = 0.0f;
    const float* wr = W + (size_t)t * K_DIM;
    for (int d = 0; d < K_DIM; ++d)
        acc = fmaf(xs[d], wr[d], acc);
    hrow[t] = acc;
    __syncthreads();

    for (int half = 1; half < MOUT; half <<= 1) {
        if (t < MOUT / 2) {
            const int j = ((t & ~(half - 1)) << 1) | (t & (half - 1));
            const float a = hrow[j];
            const float b = hrow[j + half];
            hrow[j]        = a + b;
            hrow[j + half] = a - b;
        }
        __syncthreads();
    }
    out[(size_t)row * MOUT + t] =
        (hrow[t] * 0.08838834764831844f > 0.0f) ? 1.0f : 0.0f;
}

// ---------------- launch ----------------
extern "C" void kernel_launch(void* const* d_in, const int* in_sizes, int n_in,
                              void* d_out, int out_size) {
    const float* x = (const float*)d_in[0];
    const float* W = (const float*)d_in[1];
    float* out = (float*)d_out;

    cudaFuncSetAttribute(tensor_gemm_kernel,
                         cudaFuncAttributeMaxDynamicSharedMemorySize, SM_TOTAL);

    split_w_kernel<<<(MOUT * K_DIM) / 256, 256>>>(W);
    tensor_gemm_kernel<<<NROWS / 128, 256, SM_TOTAL>>>(x, out);
    fix_rows_kernel<<<NROWS, 128>>>(x, W, out);
}